// round 5
// baseline (speedup 1.0000x reference)
#include <cuda_runtime.h>
#include <math.h>
#include <stdint.h>

// Problem constants
#define BB    64
#define TT    128
#define INW   128
#define HHD   512
#define NND   2048
#define WWD   64
#define OUTW  128
#define RRD   4
#define CTRL  384            // IN + R*W
#define KGATE 896            // CTRL + H  (14 tiles of 64)
#define JGATE 2048           // 4*H
#define JOK   448            // OUT + (R+1)*W
#define EPSF  1e-8f

#define GRID  288
#define NTHR  256

// ------------------------- persistent device state -------------------------
__device__ float g_h[BB * HHD];
__device__ float g_c[BB * HHD];
__device__ float g_M[BB * NND * WWD];          // 33.5 MB
__device__ float g_usage[BB * NND];
__device__ float g_rw[2][BB * RRD * NND];      // ping-pong read weights
__device__ float g_read_vec[BB * RRD * WWD];
__device__ float g_sim[BB * RRD * NND];
__device__ float g_Kn[BB * RRD * WWD];         // normalized read keys
__device__ float g_wkey[BB * WWD];             // write key
__device__ int   g_lu[BB];                     // argmin(usage) per batch
__device__ float g_gpart[8][BB][JGATE];        // gates k-split partials (4 MB)
__device__ float g_opart[8][BB][JOK];          // ok  k-split partials
__device__ unsigned g_count;                   // grid barrier counter

// ------------------------------- reset -------------------------------------
__global__ void k_reset() {
    long idx = (long)blockIdx.x * blockDim.x + threadIdx.x;
    if (idx < (long)BB * NND * WWD) g_M[idx] = 1e-6f;
    if (idx < BB * HHD) { g_h[idx] = 0.f; g_c[idx] = 0.f; }
    if (idx < BB * NND) g_usage[idx] = 0.f;
    if (idx < BB * RRD * NND) { g_rw[0][idx] = 0.f; g_rw[1][idx] = 0.f; }
    if (idx < BB * RRD * WWD) g_read_vec[idx] = 0.f;
    if (idx < BB) g_lu[idx] = 0;
    if (idx == 0) g_count = 0u;
}

// --------------------------- grid-wide barrier ------------------------------
__device__ __forceinline__ void gsync(unsigned target) {
    __syncthreads();
    if (threadIdx.x == 0) {
        asm volatile("red.release.gpu.add.u32 [%0], 1;" :: "l"(&g_count) : "memory");
        unsigned v;
        do {
            asm volatile("ld.acquire.gpu.u32 %0, [%1];" : "=r"(v) : "l"(&g_count) : "memory");
        } while (v < target);
    }
    __syncthreads();
}

__device__ __forceinline__ float sigm(float x) { return 1.f / (1.f + expf(-x)); }

// ------------------------------ persistent kernel ---------------------------
__global__ void __launch_bounds__(NTHR, 2) k_mann(
    const float* __restrict__ x_seq,
    const float* __restrict__ Wih,  const float* __restrict__ Whh,
    const float* __restrict__ bih,  const float* __restrict__ bhh,
    const float* __restrict__ Wout, const float* __restrict__ bout,
    const float* __restrict__ Wkey, const float* __restrict__ bkey,
    const float* __restrict__ alpha, const float* __restrict__ gamma,
    float* __restrict__ out)
{
    __shared__ __align__(16) char s_arena[34816];
    float4* xs4 = (float4*)s_arena;            // 1024 float4 = 16 KB
    float4* ws4 = ((float4*)s_arena) + 1024;   // up to 64*17 float4 = 17.4 KB

    const int tid = threadIdx.x;
    const int bx  = blockIdx.x;
    const int hq  = tid & 15;
    const int bq  = tid >> 4;
    const int wid = tid >> 5, lane = tid & 31;

    const float sa = 1.f / (1.f + expf(-alpha[0]));
    const float gm = gamma[0];

    unsigned target = 0;

    for (int t = 0; t < TT; ++t) {
        const float* xt = x_seq + (size_t)t * BB * INW;
        const int sel = t & 1;

        // ==================== phase 1: gates partial GEMM ====================
        // items: 32 j-tiles(64) x 8 k-splits of K=896 (14 tiles of 64)
        for (int it = bx; it < 32 * 8; it += GRID) {
            const int jt = it >> 3, ks = it & 7;
            const int j0 = jt * 64;
            const int t0 = (ks * 14) >> 3, t1 = ((ks + 1) * 14) >> 3;

            float acc[4][4];
#pragma unroll
            for (int g = 0; g < 4; ++g)
#pragma unroll
                for (int i = 0; i < 4; ++i) acc[g][i] = 0.f;

            for (int tl = t0; tl < t1; ++tl) {
                const int k0 = tl * 64;
#pragma unroll
                for (int li = 0; li < 4; ++li) {
                    int fid = tid + 256 * li;
                    int b = fid >> 4, kk4 = fid & 15;
                    int k = k0 + kk4 * 4;
                    const float* src;
                    if (k < INW)       src = xt + b * INW + k;
                    else if (k < CTRL) src = g_read_vec + b * (RRD * WWD) + (k - INW);
                    else               src = g_h + b * HHD + (k - CTRL);
                    xs4[fid] = *reinterpret_cast<const float4*>(src);
                }
#pragma unroll
                for (int li = 0; li < 4; ++li) {
                    int fid = tid + 256 * li;
                    int r = fid >> 4, kk4 = fid & 15;
                    int k = k0 + kk4 * 4;
                    int j = j0 + r;
                    const float* src = (k < CTRL) ? (Wih + (size_t)j * CTRL + k)
                                                  : (Whh + (size_t)j * HHD + (k - CTRL));
                    ws4[r * 17 + kk4] = *reinterpret_cast<const float4*>(src);
                }
                __syncthreads();
#pragma unroll
                for (int kk = 0; kk < 16; ++kk) {
                    float4 xv[4], wv[4];
#pragma unroll
                    for (int i = 0; i < 4; ++i) xv[i] = xs4[(bq * 4 + i) * 16 + kk];
#pragma unroll
                    for (int g = 0; g < 4; ++g) wv[g] = ws4[(g * 16 + hq) * 17 + kk];
#pragma unroll
                    for (int g = 0; g < 4; ++g)
#pragma unroll
                        for (int i = 0; i < 4; ++i)
                            acc[g][i] += xv[i].x * wv[g].x + xv[i].y * wv[g].y +
                                         xv[i].z * wv[g].z + xv[i].w * wv[g].w;
                }
                __syncthreads();
            }
#pragma unroll
            for (int g = 0; g < 4; ++g)
#pragma unroll
                for (int i = 0; i < 4; ++i)
                    g_gpart[ks][bq * 4 + i][j0 + g * 16 + hq] = acc[g][i];
        }
        target += GRID; gsync(target);

        // ==================== phase 2: LSTM pointwise (reduce partials) =====
        for (int idx = bx * NTHR + tid; idx < BB * HHD; idx += GRID * NTHR) {
            const int b = idx >> 9, hh = idx & 511;
            float s0 = bih[hh]        + bhh[hh];
            float s1 = bih[512 + hh]  + bhh[512 + hh];
            float s2 = bih[1024 + hh] + bhh[1024 + hh];
            float s3 = bih[1536 + hh] + bhh[1536 + hh];
#pragma unroll
            for (int ks = 0; ks < 8; ++ks) {
                s0 += g_gpart[ks][b][hh];
                s1 += g_gpart[ks][b][512 + hh];
                s2 += g_gpart[ks][b][1024 + hh];
                s3 += g_gpart[ks][b][1536 + hh];
            }
            float c  = g_c[idx];
            float cn = sigm(s1) * c + sigm(s0) * tanhf(s2);
            float hn = sigm(s3) * tanhf(cn);
            g_c[idx] = cn;
            g_h[idx] = hn;
        }
        target += GRID; gsync(target);

        // ==================== phase 3: out+keys partial GEMM ================
        // items: 14 j-tiles(32) x 8 k-splits(64) over K=512
        for (int it = bx; it < 14 * 8; it += GRID) {
            const int jt = it >> 3, ks = it & 7;
            const int j0 = jt * 32, k0 = ks * 64;
            float acc[2][4];
#pragma unroll
            for (int g = 0; g < 2; ++g)
#pragma unroll
                for (int i = 0; i < 4; ++i) acc[g][i] = 0.f;
#pragma unroll
            for (int li = 0; li < 4; ++li) {
                int fid = tid + 256 * li;
                int b = fid >> 4, kk4 = fid & 15;
                xs4[fid] = *reinterpret_cast<const float4*>(g_h + b * HHD + k0 + kk4 * 4);
            }
#pragma unroll
            for (int li = 0; li < 2; ++li) {
                int fid = tid + 256 * li;
                int r = fid >> 4, kk4 = fid & 15;
                int j = j0 + r, k = k0 + kk4 * 4;
                const float* src = (j < OUTW) ? (Wout + (size_t)j * HHD + k)
                                              : (Wkey + (size_t)(j - OUTW) * HHD + k);
                ws4[r * 17 + kk4] = *reinterpret_cast<const float4*>(src);
            }
            __syncthreads();
#pragma unroll
            for (int kk = 0; kk < 16; ++kk) {
                float4 xv[4], wv[2];
#pragma unroll
                for (int i = 0; i < 4; ++i) xv[i] = xs4[(bq * 4 + i) * 16 + kk];
#pragma unroll
                for (int g = 0; g < 2; ++g) wv[g] = ws4[(g * 16 + hq) * 17 + kk];
#pragma unroll
                for (int g = 0; g < 2; ++g)
#pragma unroll
                    for (int i = 0; i < 4; ++i)
                        acc[g][i] += xv[i].x * wv[g].x + xv[i].y * wv[g].y +
                                     xv[i].z * wv[g].z + xv[i].w * wv[g].w;
            }
            __syncthreads();
#pragma unroll
            for (int g = 0; g < 2; ++g)
#pragma unroll
                for (int i = 0; i < 4; ++i)
                    g_opart[ks][bq * 4 + i][j0 + g * 16 + hq] = acc[g][i];
        }
        target += GRID; gsync(target);

        // ==================== phase 4: finish (per batch) ====================
        for (int b = bx; b < BB; b += GRID) {
            __syncthreads();
            if (tid < OUTW) {
                float v = bout[tid];
#pragma unroll
                for (int ks = 0; ks < 8; ++ks) v += g_opart[ks][b][tid];
                out[(size_t)t * BB * OUTW + (size_t)b * OUTW + tid] = v;
            }
            if (wid < 5) {
                float v0 = bkey[wid * 64 + lane];
                float v1 = bkey[wid * 64 + lane + 32];
#pragma unroll
                for (int ks = 0; ks < 8; ++ks) {
                    v0 += g_opart[ks][b][OUTW + wid * 64 + lane];
                    v1 += g_opart[ks][b][OUTW + wid * 64 + lane + 32];
                }
                if (wid == 4) {
                    g_wkey[b * WWD + lane]      = v0;
                    g_wkey[b * WWD + lane + 32] = v1;
                } else {
                    float ss = v0 * v0 + v1 * v1;
#pragma unroll
                    for (int o = 16; o; o >>= 1) ss += __shfl_xor_sync(0xffffffffu, ss, o);
                    float inv = 1.f / (sqrtf(ss) + EPSF);
                    g_Kn[b * RRD * WWD + wid * 64 + lane]      = v0 * inv;
                    g_Kn[b * RRD * WWD + wid * 64 + lane + 32] = v1 * inv;
                }
            }
            // argmin over usage[b][:], first-index tie rule
            float* sv = (float*)s_arena;
            int*   si = (int*)(s_arena + 1024);
            float bv = 3.4e38f; int bi = 0;
            for (int i = tid; i < NND; i += 256) {
                float u = g_usage[b * NND + i];
                if (u < bv) { bv = u; bi = i; }
            }
            sv[tid] = bv; si[tid] = bi;
            __syncthreads();
            for (int s = 128; s; s >>= 1) {
                if (tid < s) {
                    float ov = sv[tid + s]; int oi = si[tid + s];
                    if (ov < sv[tid] || (ov == sv[tid] && oi < si[tid])) { sv[tid] = ov; si[tid] = oi; }
                }
                __syncthreads();
            }
            if (tid == 0) g_lu[b] = si[0];
            for (int i = tid; i < RRD * WWD; i += 256) g_read_vec[b * RRD * WWD + i] = 0.f;
        }
        target += GRID; gsync(target);

        // ==================== phase 5: sim ==================================
        for (int it = bx; it < BB * 32; it += GRID) {
            const int b = it >> 5, nb = it & 31;
            float* kn = (float*)s_arena;
            __syncthreads();
            if (tid < RRD * WWD) kn[tid] = g_Kn[b * RRD * WWD + tid];
            __syncthreads();
            const float2 k0 = ((const float2*)kn)[0 * 32 + lane];
            const float2 k1 = ((const float2*)kn)[1 * 32 + lane];
            const float2 k2 = ((const float2*)kn)[2 * 32 + lane];
            const float2 k3 = ((const float2*)kn)[3 * 32 + lane];
#pragma unroll
            for (int i = 0; i < 8; ++i) {
                int n = nb * 64 + wid * 8 + i;
                float2 m = ((const float2*)(g_M + (size_t)(b * NND + n) * WWD))[lane];
                float ss = m.x * m.x + m.y * m.y;
                float d0 = m.x * k0.x + m.y * k0.y;
                float d1 = m.x * k1.x + m.y * k1.y;
                float d2 = m.x * k2.x + m.y * k2.y;
                float d3 = m.x * k3.x + m.y * k3.y;
#pragma unroll
                for (int o = 16; o; o >>= 1) {
                    ss += __shfl_xor_sync(0xffffffffu, ss, o);
                    d0 += __shfl_xor_sync(0xffffffffu, d0, o);
                    d1 += __shfl_xor_sync(0xffffffffu, d1, o);
                    d2 += __shfl_xor_sync(0xffffffffu, d2, o);
                    d3 += __shfl_xor_sync(0xffffffffu, d3, o);
                }
                if (lane == 0) {
                    float inv = 1.f / (sqrtf(ss) + EPSF);
                    g_sim[(size_t)(b * RRD + 0) * NND + n] = d0 * inv;
                    g_sim[(size_t)(b * RRD + 1) * NND + n] = d1 * inv;
                    g_sim[(size_t)(b * RRD + 2) * NND + n] = d2 * inv;
                    g_sim[(size_t)(b * RRD + 3) * NND + n] = d3 * inv;
                }
            }
        }
        target += GRID; gsync(target);

        // ==================== phase 6: softmax ==============================
        for (int br = bx; br < BB * RRD; br += GRID) {
            float* red = (float*)s_arena;
            __syncthreads();
            float* rw_new = g_rw[sel];
            const float* s = g_sim + (size_t)br * NND;
            float v[8];
            float m = -3.4e38f;
#pragma unroll
            for (int j = 0; j < 8; ++j) { v[j] = s[tid + 256 * j]; m = fmaxf(m, v[j]); }
            red[tid] = m; __syncthreads();
            for (int st = 128; st; st >>= 1) { if (tid < st) red[tid] = fmaxf(red[tid], red[tid + st]); __syncthreads(); }
            m = red[0];
            __syncthreads();
            float sum = 0.f;
#pragma unroll
            for (int j = 0; j < 8; ++j) { v[j] = expf(v[j] - m); sum += v[j]; }
            red[tid] = sum; __syncthreads();
            for (int st = 128; st; st >>= 1) { if (tid < st) red[tid] += red[tid + st]; __syncthreads(); }
            float inv = 1.f / red[0];
            __syncthreads();
#pragma unroll
            for (int j = 0; j < 8; ++j)
                rw_new[(size_t)br * NND + tid + 256 * j] = v[j] * inv;
        }
        target += GRID; gsync(target);

        // ==================== phase 7: memory update ========================
        for (int it = bx; it < BB * 16; it += GRID) {
            const int b = it >> 4, cx = it & 15;
            const float* rw_new = g_rw[sel];
            const float* rw_old = g_rw[sel ^ 1];
            const int lu = g_lu[b];
            float* wk = (float*)s_arena;
            float (*red)[RRD * WWD] = (float (*)[RRD * WWD])(s_arena + 512);
            __syncthreads();
            if (tid < WWD) wk[tid] = g_wkey[b * WWD + tid];
            __syncthreads();
            const float2 wk2 = ((const float2*)wk)[lane];

            float2 a0 = {0.f, 0.f}, a1 = {0.f, 0.f}, a2 = {0.f, 0.f}, a3 = {0.f, 0.f};
#pragma unroll 4
            for (int i = 0; i < 16; ++i) {
                int n = cx * 128 + wid * 16 + i;
                size_t moff = (size_t)(b * NND + n) * WWD;
                float2 m = ((const float2*)(g_M + moff))[lane];
                float r0o = rw_old[(size_t)(b * RRD + 0) * NND + n];
                float r1o = rw_old[(size_t)(b * RRD + 1) * NND + n];
                float r2o = rw_old[(size_t)(b * RRD + 2) * NND + n];
                float r3o = rw_old[(size_t)(b * RRD + 3) * NND + n];
                float r0 = rw_new[(size_t)(b * RRD + 0) * NND + n];
                float r1 = rw_new[(size_t)(b * RRD + 1) * NND + n];
                float r2 = rw_new[(size_t)(b * RRD + 2) * NND + n];
                float r3 = rw_new[(size_t)(b * RRD + 3) * NND + n];
                float so = r0o + r1o + r2o + r3o;
                bool is_lu = (n == lu);
                float ww = sa * so + (is_lu ? (1.f - sa) : 0.f);
                float2 mn;
                mn.x = (is_lu ? 0.f : m.x) + ww * wk2.x;
                mn.y = (is_lu ? 0.f : m.y) + ww * wk2.y;
                ((float2*)(g_M + moff))[lane] = mn;
                a0.x += r0 * m.x; a0.y += r0 * m.y;
                a1.x += r1 * m.x; a1.y += r1 * m.y;
                a2.x += r2 * m.x; a2.y += r2 * m.y;
                a3.x += r3 * m.x; a3.y += r3 * m.y;
                if (lane == 0)
                    g_usage[b * NND + n] = gm * g_usage[b * NND + n] + (r0 + r1 + r2 + r3) + ww;
            }
            float* rp = red[wid];
            rp[0 * WWD + 2 * lane] = a0.x; rp[0 * WWD + 2 * lane + 1] = a0.y;
            rp[1 * WWD + 2 * lane] = a1.x; rp[1 * WWD + 2 * lane + 1] = a1.y;
            rp[2 * WWD + 2 * lane] = a2.x; rp[2 * WWD + 2 * lane + 1] = a2.y;
            rp[3 * WWD + 2 * lane] = a3.x; rp[3 * WWD + 2 * lane + 1] = a3.y;
            __syncthreads();
            if (tid < RRD * WWD) {
                float s = 0.f;
#pragma unroll
                for (int w = 0; w < 8; ++w) s += red[w][tid];
                atomicAdd(&g_read_vec[b * RRD * WWD + tid], s);
            }
        }
        target += GRID; gsync(target);
    }
}

// ------------------------------- launcher ------------------------------------
extern "C" void kernel_launch(void* const* d_in, const int* in_sizes, int n_in,
                              void* d_out, int out_size) {
    const float* x_seq = (const float*)d_in[0];
    const float* Wih   = (const float*)d_in[1];
    const float* Whh   = (const float*)d_in[2];
    const float* bih   = (const float*)d_in[3];
    const float* bhh   = (const float*)d_in[4];
    const float* Wout  = (const float*)d_in[5];
    const float* bout  = (const float*)d_in[6];
    const float* Wkey  = (const float*)d_in[7];
    const float* bkey  = (const float*)d_in[8];
    const float* alpha = (const float*)d_in[9];
    const float* gamma = (const float*)d_in[10];
    float* out = (float*)d_out;

    k_reset<<<32768, 256>>>();
    k_mann<<<GRID, NTHR>>>(x_seq, Wih, Whh, bih, bhh, Wout, bout,
                           Wkey, bkey, alpha, gamma, out);
}